// round 2
// baseline (speedup 1.0000x reference)
#include <cuda_runtime.h>
#include <cuda_bf16.h>
#include <math.h>

// Laplace diagonal recurrence:
//   out[t, i, f] = e[i] * out[t-1, i, f] + decay[i] * inp[t, f]
// T = 2048, N_S = 108, F = 256, fp32.
//
// R2: latency-bound fix. CHUNK 128->32, WARM 128->64 quadruples the grid
// (1728 blocks, ~47 warps/SM) so in-flight loads/stores cover the ~250-cyc
// L2 latency. Warm-up truncation e_max^64 ~ 1.2e-5 << 1e-3 tolerance.
// Each thread carries 4 i-states per float2 of f (1 load feeds 4 recurrences).

constexpr int T_LEN  = 2048;
constexpr int F      = 256;
constexpr int NS     = 108;
constexpr int CHUNK  = 32;
constexpr int WARM   = 64;
constexpr int NCHUNK = T_LEN / CHUNK;   // 64
constexpr int GI     = 4;               // i-values per block
constexpr int NIB    = NS / GI;         // 27 i-groups
constexpr int F2     = F / 2;           // 128 float2 lanes

__global__ __launch_bounds__(F2, 12)
void laplace_kernel(const float* __restrict__ inp, float* __restrict__ out) {
    const int f2    = threadIdx.x;   // 0..127 -> f pair
    const int ib    = blockIdx.x;    // 0..26
    const int chunk = blockIdx.y;    // 0..63

    // Per-i constants (double precision, matches reference to ~1e-8).
    float e[GI], dcy[GI];
    const double c = pow(20.0, 1.0 / 99.0) - 1.0;
    #pragma unroll
    for (int g = 0; g < GI; g++) {
        int i = ib * GI + g;
        double tau = pow(1.0 + c, (double)(i - 4));
        double s   = 4.0 / tau;
        double ed  = exp(-s);
        e[g]   = (float)ed;
        dcy[g] = (float)((1.0 - ed) / s);
    }

    const int t_start = chunk * CHUNK;
    int t0 = t_start - WARM;
    if (t0 < 0) t0 = 0;

    const float2* __restrict__ inp2 = reinterpret_cast<const float2*>(inp);
    float2* __restrict__ out2       = reinterpret_cast<float2*>(out);

    float2 st[GI];
    #pragma unroll
    for (int g = 0; g < GI; g++) st[g] = make_float2(0.f, 0.f);

    const float2* ip = inp2 + (size_t)t0 * F2 + f2;

    // Warm-up: recurrence without stores. Unrolled so loads batch (MLP).
    const int warm_steps = t_start - t0;
    #pragma unroll 8
    for (int t = 0; t < warm_steps; ++t) {
        float2 x = __ldg(ip);
        ip += F2;
        #pragma unroll
        for (int g = 0; g < GI; g++) {
            st[g].x = fmaf(e[g], st[g].x, dcy[g] * x.x);
            st[g].y = fmaf(e[g], st[g].y, dcy[g] * x.y);
        }
    }

    // Main: CHUNK rows with explicit next-row prefetch so the load issues
    // ahead of the 4 stores of the previous iteration.
    float2* op = out2 + (size_t)t_start * (NS * F2) + (size_t)(ib * GI) * F2 + f2;
    float2 x = __ldg(ip);
    ip += F2;
    #pragma unroll 4
    for (int t = 0; t < CHUNK; ++t) {
        float2 xn;
        if (t + 1 < CHUNK) { xn = __ldg(ip); ip += F2; }
        #pragma unroll
        for (int g = 0; g < GI; g++) {
            st[g].x = fmaf(e[g], st[g].x, dcy[g] * x.x);
            st[g].y = fmaf(e[g], st[g].y, dcy[g] * x.y);
            op[g * F2] = st[g];
        }
        op += NS * F2;
        x = xn;
    }
}

extern "C" void kernel_launch(void* const* d_in, const int* in_sizes, int n_in,
                              void* d_out, int out_size) {
    const float* inp = (const float*)d_in[0];
    float* out       = (float*)d_out;
    dim3 grid(NIB, NCHUNK);   // 27 x 64 = 1728 blocks
    laplace_kernel<<<grid, F2>>>(inp, out);
}

// round 3
// speedup vs baseline: 3.4309x; 3.4309x over previous
#include <cuda_runtime.h>
#include <cuda_bf16.h>
#include <math.h>

// Laplace diagonal recurrence:
//   out[t, i, f] = e[i] * out[t-1, i, f] + decay[i] * inp[t, f]
// T = 2048, N_S = 108, F = 256, fp32.
//
// R3: latency decoupling via register software pipeline (depth 8, float4
// loads), scaled recurrence (st' = e*st' + x, out = dcy*st') so warm-up is
// FFMA-only, GI=6 per block (3 i-states of float4 per thread) to cut read
// traffic. Grid = 18 i-groups x 16 chunks = 288 blocks.

constexpr int T_LEN  = 2048;
constexpr int F      = 256;
constexpr int NS     = 108;
constexpr int CHUNK  = 128;
constexpr int WARM   = 64;
constexpr int NCHUNK = T_LEN / CHUNK;   // 16
constexpr int GI     = 6;               // i-values per block
constexpr int NIB    = NS / GI;         // 18
constexpr int PF     = 8;               // prefetch depth (rows)
constexpr int F4     = F / 4;           // 64 float4 lanes per row

__global__ __launch_bounds__(128)
void laplace_kernel(const float* __restrict__ inp, float* __restrict__ out) {
    const int tid = threadIdx.x;
    const int fq  = tid & 63;        // float4 lane: f = 4*fq
    const int iq  = tid >> 6;        // 0..1 -> which half of the 6 i's
    const int ib  = blockIdx.x;      // 0..17
    const int chunk = blockIdx.y;    // 0..15

    // Per-i constants in double precision (matches reference ~1e-7).
    float e[3], dcy[3];
    const double c = pow(20.0, 1.0 / 99.0) - 1.0;
    #pragma unroll
    for (int k = 0; k < 3; k++) {
        int i = ib * GI + iq * 3 + k;
        double tau = pow(1.0 + c, (double)(i - 4));
        double s   = 4.0 / tau;
        double ed  = exp(-s);
        e[k]   = (float)ed;
        dcy[k] = (float)((1.0 - ed) / s);
    }

    const int t_start = chunk * CHUNK;
    const int warm    = (t_start < WARM) ? t_start : WARM;  // 0 or 64
    const int t0      = t_start - warm;
    const int steps   = warm + CHUNK;                        // 128 or 192

    const float4* __restrict__ ip = reinterpret_cast<const float4*>(inp)
                                    + (size_t)t0 * F4 + fq;
    float4* __restrict__ oq = reinterpret_cast<float4*>(out);

    // Scaled states: st' = e*st' + x;  out = dcy * st'.
    float4 st[3];
    #pragma unroll
    for (int k = 0; k < 3; k++) st[k] = make_float4(0.f, 0.f, 0.f, 0.f);

    // Prime the register pipeline.
    float4 pf[PF];
    #pragma unroll
    for (int j = 0; j < PF; j++) pf[j] = __ldg(ip + j * F4);

    // ---- warm-up (no stores), warm is 0 or 64, divisible by PF ----
    for (int tb = 0; tb < warm; tb += PF) {
        #pragma unroll
        for (int j = 0; j < PF; j++) {
            const int t  = tb + j;
            const float4 x = pf[j];
            const int tn = t + PF;
            if (tn < steps) pf[j] = __ldg(ip + (size_t)tn * F4);
            #pragma unroll
            for (int k = 0; k < 3; k++) {
                st[k].x = fmaf(e[k], st[k].x, x.x);
                st[k].y = fmaf(e[k], st[k].y, x.y);
                st[k].z = fmaf(e[k], st[k].z, x.z);
                st[k].w = fmaf(e[k], st[k].w, x.w);
            }
        }
    }

    // ---- main: CHUNK=128 stored rows ----
    // out float4 index: ((t_start+tr)*NS + i)*F4 + fq
    size_t obase = ((size_t)t_start * NS + (size_t)(ib * GI + iq * 3)) * F4 + fq;
    for (int tb = 0; tb < CHUNK; tb += PF) {
        #pragma unroll
        for (int j = 0; j < PF; j++) {
            const int tr = tb + j;          // 0..127
            const int t  = warm + tr;
            const float4 x = pf[j];
            const int tn = t + PF;
            if (tn < steps) pf[j] = __ldg(ip + (size_t)tn * F4);
            #pragma unroll
            for (int k = 0; k < 3; k++) {
                st[k].x = fmaf(e[k], st[k].x, x.x);
                st[k].y = fmaf(e[k], st[k].y, x.y);
                st[k].z = fmaf(e[k], st[k].z, x.z);
                st[k].w = fmaf(e[k], st[k].w, x.w);
                float4 o;
                o.x = dcy[k] * st[k].x;
                o.y = dcy[k] * st[k].y;
                o.z = dcy[k] * st[k].z;
                o.w = dcy[k] * st[k].w;
                oq[obase + (size_t)tr * (NS * F4) + (size_t)k * F4] = o;
            }
        }
    }
}

extern "C" void kernel_launch(void* const* d_in, const int* in_sizes, int n_in,
                              void* d_out, int out_size) {
    const float* inp = (const float*)d_in[0];
    float* out       = (float*)d_out;
    dim3 grid(NIB, NCHUNK);   // 18 x 16 = 288 blocks
    laplace_kernel<<<grid, 128>>>(inp, out);
}